// round 10
// baseline (speedup 1.0000x reference)
#include <cuda_runtime.h>
#include <cstdint>

// Problem dims
#define BB 4
#define MM 512
#define NN 512
#define KK 128

// Decoded scratch, m-major (same layout as logical input): g_dA[b][m][k]
__device__ __align__(16) float g_dA[BB * MM * KK];
__device__ __align__(16) float g_dB[BB * NN * KK];

// ---------------------------------------------------------------------------
// Kernel 1: decode 8-pulse FP8 E4M3 codes -> fp32, m-major output.
// Reads coalesced via lane-consecutive codes, smem exchange, then each warp
// writes one full row chunk (512B contiguous float4s along k).
// Exact decode: power-of-two via exponent field; (1+m/8) exact.
// ---------------------------------------------------------------------------
#define DEC_R 8

__global__ __launch_bounds__(256) void decode_kernel(const float4* __restrict__ inA,
                                                     const float4* __restrict__ inB) {
    __shared__ float s[KK][DEC_R + 1];  // [k][r], pad -> conflict-free-ish

    const int blk = blockIdx.x;                 // 0..511
    const bool isB = blk >= 256;
    const int sub = isB ? (blk - 256) : blk;    // 0..255
    const int b  = sub >> 6;                    // batch
    const int r0 = (sub & 63) * DEC_R;          // row-block start

    const float4* __restrict__ in = isB ? inB : inA;
    float* __restrict__ outp = isB ? g_dB : g_dA;

    const int tid = threadIdx.x;
    const long gbase = ((long)(b * MM + r0)) * KK;

#pragma unroll
    for (int j = 0; j < 4; j++) {
        int c = j * 256 + tid;           // r_local = c>>7, k = c&127
        float4 p0 = in[(gbase + c) * 2];
        float4 p1 = in[(gbase + c) * 2 + 1];

        float ef = p0.y * 8.0f + p0.z * 4.0f + p0.w * 2.0f + p1.x;
        float mf = p1.y * 4.0f + p1.z * 2.0f + p1.w;
        int e = (int)ef;

        float mag;
        if (e > 0) {
            mag = __uint_as_float((unsigned)(e + 120) << 23) * (1.0f + mf * 0.125f);
        } else {
            mag = mf * (1.0f / 512.0f);  // subnormal: m * 2^-9
        }
        float val = (p0.x > 0.5f) ? -mag : mag;

        s[c & (KK - 1)][c >> 7] = val;
    }
    __syncthreads();

    // m-major write: warp w handles row r0+w? -> tid>>5 = r (0..7),
    // lane = k4 (0..31): one row = 512B contiguous per warp.
    {
        int r  = tid >> 5;
        int k4 = (tid & 31) * 4;
        float4 v;
        v.x = s[k4 + 0][r];
        v.y = s[k4 + 1][r];
        v.z = s[k4 + 2][r];
        v.w = s[k4 + 3][r];
        *(float4*)&outp[((long)(b * MM + r0 + r)) * KK + k4] = v;
    }
}

// ---------------------------------------------------------------------------
// Kernel 2: FUSED batched GEMM + bit-plane encode.
// 32x32 C tile per CTA (grid=1024, ~7/SM -> single resident wave), 256 thr,
// 2x2 micro-tile on rows {ty,ty+16} x cols {tx,tx+16}.
// Smem tiles row-major [m][k] stride 68 (pad 4) -> inner loop loads float4
// along k: 4x LDS.128 per 4 k-steps (half the LDS instrs of k-major float2),
// bank-conflict-free (b rows tx/tx+16 -> phase banks 4*tx mod 32 distinct).
// STRICT sequential-k fp32 FMA accumulation per element (k ascending through
// chunks, then x,y,z,w) -- DO NOT reassociate; bit-exactness depends on it.
// Encode phase: stage C in smem, lane-contiguous STG.128 with __stcs.
// ---------------------------------------------------------------------------
#define BMT 32
#define BNT 32
#define KCH 64
#define SP  68   // padded smem row stride (floats)

__global__ __launch_bounds__(256, 7) void gemm_encode_kernel(float4* __restrict__ out) {
    __shared__ float As[BMT][SP];   // 8.5 KB
    __shared__ float Bs[BNT][SP];   // 8.5 KB

    const int b   = blockIdx.z;
    const int tm0 = blockIdx.y * BMT;
    const int tn0 = blockIdx.x * BNT;
    const int tid = threadIdx.x;
    const int tx  = tid & 15;        // n selector: cols {tx, tx+16}
    const int ty  = tid >> 4;        // m selector: rows {ty, ty+16}

    const float* __restrict__ Ab = g_dA + (long)b * MM * KK;
    const float* __restrict__ Bb = g_dB + (long)b * NN * KK;

    float acc00 = 0.0f, acc01 = 0.0f, acc10 = 0.0f, acc11 = 0.0f;

#pragma unroll
    for (int k0 = 0; k0 < KK; k0 += KCH) {
        // Load 32 rows x 64 k per tile: 512 float4 / 256 threads = 2 each.
#pragma unroll
        for (int i = 0; i < 2; i++) {
            int w  = i * 256 + tid;
            int m  = w >> 4;              // row 0..31
            int c4 = (w & 15) * 4;        // k offset within chunk
            *(float4*)&As[m][c4] = *(const float4*)&Ab[(long)(tm0 + m) * KK + k0 + c4];
            *(float4*)&Bs[m][c4] = *(const float4*)&Bb[(long)(tn0 + m) * KK + k0 + c4];
        }
        __syncthreads();

        // 16 float4 k-steps; within each, k ascends x,y,z,w. Each accumulator
        // is a single sequential fmaf chain over all k (bit-exact order).
#pragma unroll
        for (int kk = 0; kk < 16; kk++) {
            float4 a0 = *(const float4*)&As[ty][kk * 4];
            float4 a1 = *(const float4*)&As[ty + 16][kk * 4];
            float4 b0 = *(const float4*)&Bs[tx][kk * 4];
            float4 b1 = *(const float4*)&Bs[tx + 16][kk * 4];

            acc00 = fmaf(a0.x, b0.x, acc00);
            acc01 = fmaf(a0.x, b1.x, acc01);
            acc10 = fmaf(a1.x, b0.x, acc10);
            acc11 = fmaf(a1.x, b1.x, acc11);

            acc00 = fmaf(a0.y, b0.y, acc00);
            acc01 = fmaf(a0.y, b1.y, acc01);
            acc10 = fmaf(a1.y, b0.y, acc10);
            acc11 = fmaf(a1.y, b1.y, acc11);

            acc00 = fmaf(a0.z, b0.z, acc00);
            acc01 = fmaf(a0.z, b1.z, acc01);
            acc10 = fmaf(a1.z, b0.z, acc10);
            acc11 = fmaf(a1.z, b1.z, acc11);

            acc00 = fmaf(a0.w, b0.w, acc00);
            acc01 = fmaf(a0.w, b1.w, acc01);
            acc10 = fmaf(a1.w, b0.w, acc10);
            acc11 = fmaf(a1.w, b1.w, acc11);
        }
        __syncthreads();
    }

    // Stage C tile into smem (reuse As: Cs[m][n] in the first 32 cols).
    As[ty][tx]           = acc00;
    As[ty][tx + 16]      = acc01;
    As[ty + 16][tx]      = acc10;
    As[ty + 16][tx + 16] = acc11;
    __syncthreads();

    // Encode + store: tile covers 256 contiguous float4 per output row.
    // Thread t: n_local = t>>3, nibble q = t&7; lanes contiguous (512B/warp).
    const unsigned base0 = ((unsigned)((b * MM + tm0) * NN + tn0)) * 8u;
    const unsigned q  = (unsigned)(tid & 7);
    const unsigned s0 = 28u - 4u * q;        // bit pos of .w
    const int nl = tid >> 3;

#pragma unroll 4
    for (int ml = 0; ml < BMT; ml++) {
        unsigned u = __float_as_uint(As[ml][nl]);
        float4 v;
        v.x = ((u >> (s0 + 3)) & 1u) ? 1.0f : 0.0f;
        v.y = ((u >> (s0 + 2)) & 1u) ? 1.0f : 0.0f;
        v.z = ((u >> (s0 + 1)) & 1u) ? 1.0f : 0.0f;
        v.w = ((u >> (s0 + 0)) & 1u) ? 1.0f : 0.0f;
        __stcs(&out[base0 + (unsigned)ml * (NN * 8u) + (unsigned)tid], v);
    }
}

extern "C" void kernel_launch(void* const* d_in, const int* in_sizes, int n_in,
                              void* d_out, int out_size) {
    const float4* A = (const float4*)d_in[0];
    const float4* B = (const float4*)d_in[1];

    decode_kernel<<<512, 256>>>(A, B);

    dim3 grid(NN / BNT, MM / BMT, BB);  // (16, 16, 4) = 1024 CTAs
    gemm_encode_kernel<<<grid, 256>>>((float4*)d_out);
}

// round 12
// speedup vs baseline: 1.0852x; 1.0852x over previous
#include <cuda_runtime.h>
#include <cstdint>

// Problem dims
#define BB 4
#define MM 512
#define NN 512
#define KK 128

// Decoded scratch, k-major per batch: g_dA[b][k][m], g_dB[b][k][n]
__device__ __align__(16) float g_dA[BB * KK * MM];
__device__ __align__(16) float g_dB[BB * KK * NN];

// ---------------------------------------------------------------------------
// Kernel 1: decode 8-pulse FP8 E4M3 codes -> fp32, k-major output via smem
// transpose. Proven R7 config: 256 threads, DEC_R=8, grid=512 (6.9us).
// Exact decode: power-of-two via exponent field; (1+m/8) exact.
// ---------------------------------------------------------------------------
#define DEC_R 8

__global__ __launch_bounds__(256) void decode_kernel(const float4* __restrict__ inA,
                                                     const float4* __restrict__ inB) {
    __shared__ float s[KK][DEC_R + 1];  // pad -> conflict-free

    const int blk = blockIdx.x;                 // 0..511
    const bool isB = blk >= 256;
    const int sub = isB ? (blk - 256) : blk;    // 0..255
    const int b  = sub >> 6;                    // batch (64 row-blocks/batch)
    const int r0 = (sub & 63) * DEC_R;          // row-block start

    const float4* __restrict__ in = isB ? inB : inA;
    float* __restrict__ outp = isB ? g_dB : g_dA;

    const int tid = threadIdx.x;
    const long gbase = ((long)(b * MM + r0)) * KK;

    // Decode 4 codes per thread; input fully coalesced (32B per code).
#pragma unroll
    for (int j = 0; j < 4; j++) {
        int c = j * 256 + tid;           // 0..1023: r_local = c>>7, k = c&127
        float4 p0 = in[(gbase + c) * 2];
        float4 p1 = in[(gbase + c) * 2 + 1];

        float ef = p0.y * 8.0f + p0.z * 4.0f + p0.w * 2.0f + p1.x;
        float mf = p1.y * 4.0f + p1.z * 2.0f + p1.w;
        int e = (int)ef;

        float mag;
        if (e > 0) {
            mag = __uint_as_float((unsigned)(e + 120) << 23) * (1.0f + mf * 0.125f);
        } else {
            mag = mf * (1.0f / 512.0f);  // subnormal: m * 2^-9
        }
        float val = (p0.x > 0.5f) ? -mag : mag;

        s[c & (KK - 1)][c >> 7] = val;
    }
    __syncthreads();

    // Write k-major: 128 k-rows x 2 float4 = 256 float4, one per thread.
    // 32B contiguous per k-row (full sectors).
    {
        int k  = tid >> 1;
        int r4 = (tid & 1) * 4;
        float4 v;
        v.x = s[k][r4 + 0];
        v.y = s[k][r4 + 1];
        v.z = s[k][r4 + 2];
        v.w = s[k][r4 + 3];
        *(float4*)&outp[(b * KK + k) * MM + r0 + r4] = v;
    }
}

// ---------------------------------------------------------------------------
// Kernel 2: FUSED batched GEMM + bit-plane encode (R9 body, byte-identical).
// 32x32 C tile per CTA (grid=1024), 256 threads, 2x2 micro-tile.
// ONLY change vs R9: __launch_bounds__(256, 7) -> 7 CTAs/SM -> all 1024 CTAs
// resident in ONE wave (R9 regs=38 capped at 6/SM -> 136-CTA store tail wave).
// STRICT sequential-k fp32 FMA accumulation (single accumulator, k ascending)
// -- DO NOT reassociate; bit-exactness vs reference depends on this.
// ---------------------------------------------------------------------------
#define BMT 32
#define BNT 32
#define KCH 64

__global__ __launch_bounds__(256, 7) void gemm_encode_kernel(float4* __restrict__ out) {
    __shared__ float As[KCH][BMT];   // 8 KB
    __shared__ float Bs[KCH][BNT];   // 8 KB

    const int b   = blockIdx.z;
    const int tm0 = blockIdx.y * BMT;
    const int tn0 = blockIdx.x * BNT;
    const int tid = threadIdx.x;
    const int tx  = tid & 15;        // n pair selector (2 cols)
    const int ty  = tid >> 4;        // m pair selector (2 rows)

    const float* __restrict__ Ab = g_dA + b * KK * MM;
    const float* __restrict__ Bb = g_dB + b * KK * NN;

    float acc00 = 0.0f, acc01 = 0.0f, acc10 = 0.0f, acc11 = 0.0f;

#pragma unroll
    for (int k0 = 0; k0 < KK; k0 += KCH) {
        // Load 64k x 32 tiles of A and B: 512 float4 each / 256 threads = 2.
#pragma unroll
        for (int i = 0; i < 2; i++) {
            int w  = i * 256 + tid;
            int r  = w >> 3;
            int c4 = (w & 7) * 4;
            *(float4*)&As[r][c4] = *(const float4*)&Ab[(k0 + r) * MM + tm0 + c4];
            *(float4*)&Bs[r][c4] = *(const float4*)&Bb[(k0 + r) * NN + tn0 + c4];
        }
        __syncthreads();

        // Sequential over k (ascending), single accumulator per element.
#pragma unroll
        for (int k = 0; k < KCH; k++) {
            float2 a2 = *(const float2*)&As[k][ty * 2];
            float2 b2 = *(const float2*)&Bs[k][tx * 2];
            acc00 = fmaf(a2.x, b2.x, acc00);
            acc01 = fmaf(a2.x, b2.y, acc01);
            acc10 = fmaf(a2.y, b2.x, acc10);
            acc11 = fmaf(a2.y, b2.y, acc11);
        }
        __syncthreads();
    }

    // Stage C tile into smem (reuse As rows 0..31: 32x32 floats = 4 KB).
    float (*Cs)[BMT] = As;
    *(float2*)&Cs[ty * 2 + 0][tx * 2] = make_float2(acc00, acc01);
    *(float2*)&Cs[ty * 2 + 1][tx * 2] = make_float2(acc10, acc11);
    __syncthreads();

    // Encode + store. Tile covers 256 contiguous float4 per output row.
    // Thread t: n_local = t>>3, nibble q = t&7; lanes contiguous (512B/warp).
    const unsigned base0 = ((unsigned)((b * MM + tm0) * NN + tn0)) * 8u;
    const unsigned q = (unsigned)(tid & 7);
    const unsigned s0 = 28u - 4u * q;        // bit pos of .w
    const int nl = tid >> 3;

#pragma unroll 4
    for (int ml = 0; ml < BMT; ml++) {
        unsigned u = __float_as_uint(Cs[ml][nl]);
        float4 v;
        v.x = ((u >> (s0 + 3)) & 1u) ? 1.0f : 0.0f;
        v.y = ((u >> (s0 + 2)) & 1u) ? 1.0f : 0.0f;
        v.z = ((u >> (s0 + 1)) & 1u) ? 1.0f : 0.0f;
        v.w = ((u >> (s0 + 0)) & 1u) ? 1.0f : 0.0f;
        __stcs(&out[base0 + (unsigned)ml * (NN * 8u) + (unsigned)tid], v);
    }
}

extern "C" void kernel_launch(void* const* d_in, const int* in_sizes, int n_in,
                              void* d_out, int out_size) {
    const float4* A = (const float4*)d_in[0];
    const float4* B = (const float4*)d_in[1];

    decode_kernel<<<512, 256>>>(A, B);

    dim3 grid(NN / BNT, MM / BMT, BB);  // (16, 16, 4) = 1024 CTAs
    gemm_encode_kernel<<<grid, 256>>>((float4*)d_out);
}

// round 13
// speedup vs baseline: 1.0892x; 1.0037x over previous
#include <cuda_runtime.h>
#include <cstdint>

// Problem dims
#define BB 4
#define MM 512
#define NN 512
#define KK 128

// Decoded scratch, k-major per batch: g_dA[b][k][m], g_dB[b][k][n]
__device__ __align__(16) float g_dA[BB * KK * MM];
__device__ __align__(16) float g_dB[BB * KK * NN];

// ---------------------------------------------------------------------------
// Kernel 1: decode 8-pulse FP8 E4M3 codes -> fp32, k-major output via smem
// transpose. Proven R7 config: 256 threads, DEC_R=8, grid=512 (6.9us).
// Exact decode: power-of-two via exponent field; (1+m/8) exact.
// ---------------------------------------------------------------------------
#define DEC_R 8

__global__ __launch_bounds__(256) void decode_kernel(const float4* __restrict__ inA,
                                                     const float4* __restrict__ inB) {
    __shared__ float s[KK][DEC_R + 1];  // pad -> conflict-free

    const int blk = blockIdx.x;                 // 0..511
    const bool isB = blk >= 256;
    const int sub = isB ? (blk - 256) : blk;    // 0..255
    const int b  = sub >> 6;                    // batch (64 row-blocks/batch)
    const int r0 = (sub & 63) * DEC_R;          // row-block start

    const float4* __restrict__ in = isB ? inB : inA;
    float* __restrict__ outp = isB ? g_dB : g_dA;

    const int tid = threadIdx.x;
    const long gbase = ((long)(b * MM + r0)) * KK;

#pragma unroll
    for (int j = 0; j < 4; j++) {
        int c = j * 256 + tid;           // r_local = c>>7, k = c&127
        float4 p0 = in[(gbase + c) * 2];
        float4 p1 = in[(gbase + c) * 2 + 1];

        float ef = p0.y * 8.0f + p0.z * 4.0f + p0.w * 2.0f + p1.x;
        float mf = p1.y * 4.0f + p1.z * 2.0f + p1.w;
        int e = (int)ef;

        float mag;
        if (e > 0) {
            mag = __uint_as_float((unsigned)(e + 120) << 23) * (1.0f + mf * 0.125f);
        } else {
            mag = mf * (1.0f / 512.0f);  // subnormal: m * 2^-9
        }
        float val = (p0.x > 0.5f) ? -mag : mag;

        s[c & (KK - 1)][c >> 7] = val;
    }
    __syncthreads();

    {
        int k  = tid >> 1;
        int r4 = (tid & 1) * 4;
        float4 v;
        v.x = s[k][r4 + 0];
        v.y = s[k][r4 + 1];
        v.z = s[k][r4 + 2];
        v.w = s[k][r4 + 3];
        *(float4*)&outp[(b * KK + k) * MM + r0 + r4] = v;
    }
}

// ---------------------------------------------------------------------------
// Kernel 2: FUSED batched GEMM + bit-plane encode.
// 64x32 C tile per CTA (grid=512, 4 CTAs/SM -> ONE wave), 256 threads,
// 4x2 micro-tile: per k, 1 LDS.128 (A, broadcast) + 1 LDS.64 (B) feeds 8 FMA
// -- halves inner-loop LSU wavefronts vs the 2x2 R12 version.
// Full-K smem tiles (48KB): single load phase (12 LDG.128/thread up front),
// no mid-loop barrier. launch_bounds(256,4) -> 64-reg budget for pipelining.
// STRICT sequential-k fp32 FMA accumulation (single accumulator per element,
// k=0..127 ascending, one term per k) -- DO NOT reassociate; bit-exactness
// vs reference depends on this.
// Encode: stage C in smem, lane-contiguous STG.128 with __stcs.
// ---------------------------------------------------------------------------
#define BMT 64
#define BNT 32

__global__ __launch_bounds__(256, 4) void gemm_encode_kernel(float4* __restrict__ out) {
    __shared__ float As[KK][BMT];   // 32 KB, k-major [k][m]
    __shared__ float Bs[KK][BNT];   // 16 KB, k-major [k][n]

    const int b   = blockIdx.z;
    const int tm0 = blockIdx.y * BMT;
    const int tn0 = blockIdx.x * BNT;
    const int tid = threadIdx.x;
    const int tx  = tid & 15;        // n selector: cols tx*2, tx*2+1
    const int ty  = tid >> 4;        // m selector: rows ty*4 .. ty*4+3

    const float* __restrict__ Ab = g_dA + b * KK * MM;
    const float* __restrict__ Bb = g_dB + b * KK * NN;

    // Load full-K tiles: A 128x64 (2048 float4, 8/thread), B 128x32 (4/thread).
#pragma unroll
    for (int i = 0; i < 8; i++) {
        int w  = i * 256 + tid;
        int r  = w >> 4;              // k row 0..127
        int c4 = (w & 15) * 4;        // m offset
        *(float4*)&As[r][c4] = *(const float4*)&Ab[r * MM + tm0 + c4];
    }
#pragma unroll
    for (int i = 0; i < 4; i++) {
        int w  = i * 256 + tid;
        int r  = w >> 3;              // k row 0..127
        int c4 = (w & 7) * 4;         // n offset
        *(float4*)&Bs[r][c4] = *(const float4*)&Bb[r * NN + tn0 + c4];
    }
    __syncthreads();

    float acc[4][2];
#pragma unroll
    for (int i = 0; i < 4; i++) { acc[i][0] = 0.0f; acc[i][1] = 0.0f; }

    // Sequential over k (ascending), single accumulator per element.
#pragma unroll 16
    for (int k = 0; k < KK; k++) {
        float4 a4 = *(const float4*)&As[k][ty * 4];
        float2 b2 = *(const float2*)&Bs[k][tx * 2];
        acc[0][0] = fmaf(a4.x, b2.x, acc[0][0]);
        acc[0][1] = fmaf(a4.x, b2.y, acc[0][1]);
        acc[1][0] = fmaf(a4.y, b2.x, acc[1][0]);
        acc[1][1] = fmaf(a4.y, b2.y, acc[1][1]);
        acc[2][0] = fmaf(a4.z, b2.x, acc[2][0]);
        acc[2][1] = fmaf(a4.z, b2.y, acc[2][1]);
        acc[3][0] = fmaf(a4.w, b2.x, acc[3][0]);
        acc[3][1] = fmaf(a4.w, b2.y, acc[3][1]);
    }
    __syncthreads();  // all reads of As done before reuse as Cs

    // Stage C tile into smem: Cs[64][32] overlaid on As.
    float* Cs = &As[0][0];
#pragma unroll
    for (int i = 0; i < 4; i++) {
        *(float2*)&Cs[(ty * 4 + i) * BNT + tx * 2] = make_float2(acc[i][0], acc[i][1]);
    }
    __syncthreads();

    // Encode + store: tile covers 256 contiguous float4 per output row, 64 rows.
    // Thread t: n_local = t>>3, nibble q = t&7; lanes contiguous (512B/warp).
    const unsigned base0 = ((unsigned)((b * MM + tm0) * NN + tn0)) * 8u;
    const unsigned q  = (unsigned)(tid & 7);
    const unsigned s0 = 28u - 4u * q;        // bit pos of .w
    const int nl = tid >> 3;

#pragma unroll 4
    for (int ml = 0; ml < BMT; ml++) {
        unsigned u = __float_as_uint(Cs[ml * BNT + nl]);
        float4 v;
        v.x = ((u >> (s0 + 3)) & 1u) ? 1.0f : 0.0f;
        v.y = ((u >> (s0 + 2)) & 1u) ? 1.0f : 0.0f;
        v.z = ((u >> (s0 + 1)) & 1u) ? 1.0f : 0.0f;
        v.w = ((u >> (s0 + 0)) & 1u) ? 1.0f : 0.0f;
        __stcs(&out[base0 + (unsigned)ml * (NN * 8u) + (unsigned)tid], v);
    }
}

extern "C" void kernel_launch(void* const* d_in, const int* in_sizes, int n_in,
                              void* d_out, int out_size) {
    const float4* A = (const float4*)d_in[0];
    const float4* B = (const float4*)d_in[1];

    decode_kernel<<<512, 256>>>(A, B);

    dim3 grid(NN / BNT, MM / BMT, BB);  // (16, 8, 4) = 512 CTAs
    gemm_encode_kernel<<<grid, 256>>>((float4*)d_out);
}